// round 11
// baseline (speedup 1.0000x reference)
#include <cuda_runtime.h>
#include <cstddef>

// YOLOv3 head decode, fused, anchor-grouped mapping, 96-thread blocks.
// Block = 96 threads = 32 consecutive positions x 3 anchors of one (b,level).
// Warp = one anchor -> plane loads perfectly coalesced (128B/warp).
// Scores staged via static smem in 16-class chunks (80B rows, 16B-aligned,
// conflict-free). Box store folded into chunk-0 store phase.
// 21 blocks/SM residency target (9.2KB smem, 32 regs).
// Output: d_out = [boxes 16*22743*4][scores 16*22743*80].

#define NCLS 80
#define NTOT 22743
#define BATCH 16
#define EPSV 1e-7f
#define BLK 96
#define POSB 32               // positions per block
#define LBLK 239              // blocks per batch: 12 + 46 + 181
#define SROW 20               // smem words per row per 16-class chunk (+4 pad)
#define SBOX (BLK * SROW)     // box buffer offset (words)

__constant__ float c_anch[3][3][2] = {
    {{116.0f, 90.0f}, {156.0f, 198.0f}, {373.0f, 326.0f}},
    {{ 30.0f, 61.0f}, { 62.0f,  45.0f}, { 59.0f, 119.0f}},
    {{ 10.0f, 13.0f}, { 16.0f,  30.0f}, { 33.0f,  23.0f}},
};

__device__ __forceinline__ float sigmoidf_fast(float x) {
    return __fdividef(1.0f, 1.0f + __expf(-x));
}

__global__ __launch_bounds__(BLK)
void yolo_fused_kernel(const float* __restrict__ in0,
                       const float* __restrict__ in1,
                       const float* __restrict__ in2,
                       const float* __restrict__ im_size,
                       float* __restrict__ boxes,
                       float* __restrict__ scores)
{
    __shared__ float s[SBOX + BLK * 4];   // 9.2 KB

    const int tid = threadIdx.x;
    const int b   = blockIdx.x / LBLK;
    const int lid = blockIdx.x - b * LBLK;

    int level, pos0, HW, Wd, stride, off;
    const float* in;
    if (lid < 12)       { level = 0; pos0 = lid * POSB;         HW = 361;  Wd = 19; stride = 32; off = 0;    in = in0; }
    else if (lid < 58)  { level = 1; pos0 = (lid - 12) * POSB;  HW = 1444; Wd = 38; stride = 16; off = 1083; in = in1; }
    else                { level = 2; pos0 = (lid - 58) * POSB;  HW = 5776; Wd = 76; stride = 8;  off = 5415; in = in2; }

    const int a   = tid / POSB;            // warp-pure anchor id
    const int i   = tid - a * POSB;
    const int pos = pos0 + i;
    const bool valid = (pos < HW);
    const int valid_rows = min(BLK, (HW - pos0) * 3);
    const int row_local  = i * 3 + a;
    const size_t row0 = (size_t)b * NTOT + off + (size_t)pos0 * 3;

    float conf = 0.0f;
    const float* p = in0;   // class-prob base for this thread's row

    if (valid) {
        const float* inb = in + (size_t)b * 258 * HW;

        float ip = sigmoidf_fast(inb[(size_t)a * HW + pos]);

        const float* f = inb + (size_t)(3 + a * 85) * HW + pos;
        float dx   = f[0];
        float dy   = f[(size_t)1 * HW];
        float dw   = f[(size_t)2 * HW];
        float dh   = f[(size_t)3 * HW];
        float tobj = f[(size_t)4 * HW];

        float obj = sigmoidf_fast(tobj);
        // new_obj = obj^0.6 * ip^0.4 (both strictly in (0,1))
        float new_obj = exp2f(0.6f * __log2f(obj) + 0.4f * __log2f(ip));
        // sigmoid(de_sigmoid(x)) == x for x in (EPS, 1-EPS); inputs are
        // N(0,1) so new_obj stays far from both clip edges.
        conf = fminf(fmaxf(new_obj, EPSV), 1.0f);

        int hh = pos / Wd;
        int ww = pos - hh * Wd;
        float x = (1.05f * sigmoidf_fast(dx) + (float)ww - 0.025f) * (float)stride;
        float y = (1.05f * sigmoidf_fast(dy) + (float)hh - 0.025f) * (float)stride;
        float bw = __expf(dw) * c_anch[level][a][0];
        float bh = __expf(dh) * c_anch[level][a][1];

        float imh = im_size[b * 2 + 0];
        float imw = im_size[b * 2 + 1];
        const float inv = 1.0f / 608.0f;   // H*stride = 608 for all levels
        float sx = imw * inv;
        float sy = imh * inv;

        float x0 = fmaxf((x - 0.5f * bw) * sx, 0.0f);
        float y0 = fmaxf((y - 0.5f * bh) * sy, 0.0f);
        float x1 = fminf((x + 0.5f * bw) * sx, imw);
        float y1 = fminf((y + 0.5f * bh) * sy, imh);

        *reinterpret_cast<float4*>(&s[SBOX + row_local * 4]) =
            make_float4(x0, y0, x1, y1);

        p = f + (size_t)5 * HW;
    }

    // scores: 5 chunks of 16 classes, staged through smem
    #pragma unroll
    for (int c0 = 0; c0 < NCLS; c0 += 16) {
        if (valid) {
            #pragma unroll
            for (int g = 0; g < 4; ++g) {
                int c = c0 + g * 4;
                float4 v;
                v.x = conf * sigmoidf_fast(p[(size_t)(c + 0) * HW]);
                v.y = conf * sigmoidf_fast(p[(size_t)(c + 1) * HW]);
                v.z = conf * sigmoidf_fast(p[(size_t)(c + 2) * HW]);
                v.w = conf * sigmoidf_fast(p[(size_t)(c + 3) * HW]);
                *reinterpret_cast<float4*>(&s[row_local * SROW + g * 4]) = v;
            }
        }
        __syncthreads();

        if (c0 == 0 && tid < valid_rows) {   // coalesced box store, once
            float4 v = *reinterpret_cast<const float4*>(&s[SBOX + tid * 4]);
            *reinterpret_cast<float4*>(&boxes[(row0 + tid) * 4]) = v;
        }

        // write BLK rows x 16 floats: 4 lanes/row, 64B runs
        #pragma unroll
        for (int k = 0; k < 4; ++k) {
            int idx = tid + k * BLK;
            int rr  = idx >> 2;
            int q   = idx & 3;
            if (rr < valid_rows) {
                float4 v = *reinterpret_cast<const float4*>(&s[rr * SROW + q * 4]);
                *reinterpret_cast<float4*>(&scores[(row0 + rr) * NCLS + c0 + q * 4]) = v;
            }
        }
        __syncthreads();
    }
}

extern "C" void kernel_launch(void* const* d_in, const int* in_sizes, int n_in,
                              void* d_out, int out_size)
{
    const float* out0 = (const float*)d_in[0];
    const float* out1 = (const float*)d_in[1];
    const float* out2 = (const float*)d_in[2];
    const float* imsz = (const float*)d_in[3];

    float* boxes  = (float*)d_out;
    float* scores = boxes + (size_t)BATCH * NTOT * 4;

    yolo_fused_kernel<<<BATCH * LBLK, BLK>>>(out0, out1, out2, imsz, boxes, scores);
}

// round 13
// speedup vs baseline: 1.0698x; 1.0698x over previous
#include <cuda_runtime.h>
#include <cstddef>

// YOLOv3 head decode, fused, anchor-grouped, monolithic smem staging.
// Block = 96 threads = 32 consecutive positions x 3 anchors of one (b,level).
// Warp = one anchor -> plane loads perfectly coalesced (128B/warp).
// All 80 classes staged in smem (stride-84 rows, conflict-free STS.128),
// ONE barrier, then a dense linear store sweep: every STG.128 covers 4 full
// 128B lines (wavefront floor). Boxes staged alongside, stored in same phase.
// Output: d_out = [boxes 16*22743*4][scores 16*22743*80].
// (Resubmission: previous round hit broker-side container failure.)

#define NCLS 80
#define NTOT 22743
#define BATCH 16
#define EPSV 1e-7f
#define BLK 96
#define POSB 32               // positions per block
#define LBLK 239              // blocks per batch: 12 + 46 + 181
#define SSTR 84               // smem words per row (336B, 16B-aligned, swizzle-free)
#define SBOX (BLK * SSTR)     // box buffer offset (words)

__constant__ float c_anch[3][3][2] = {
    {{116.0f, 90.0f}, {156.0f, 198.0f}, {373.0f, 326.0f}},
    {{ 30.0f, 61.0f}, { 62.0f,  45.0f}, { 59.0f, 119.0f}},
    {{ 10.0f, 13.0f}, { 16.0f,  30.0f}, { 33.0f,  23.0f}},
};

__device__ __forceinline__ float sigmoidf_fast(float x) {
    return __fdividef(1.0f, 1.0f + __expf(-x));
}

__global__ __launch_bounds__(BLK)
void yolo_fused_kernel(const float* __restrict__ in0,
                       const float* __restrict__ in1,
                       const float* __restrict__ in2,
                       const float* __restrict__ im_size,
                       float* __restrict__ boxes,
                       float* __restrict__ scores)
{
    __shared__ float s[SBOX + BLK * 4];   // 33.9 KB

    const int tid = threadIdx.x;
    const int b   = blockIdx.x / LBLK;
    const int lid = blockIdx.x - b * LBLK;

    int level, pos0, HW, Wd, stride, off;
    const float* in;
    if (lid < 12)       { level = 0; pos0 = lid * POSB;         HW = 361;  Wd = 19; stride = 32; off = 0;    in = in0; }
    else if (lid < 58)  { level = 1; pos0 = (lid - 12) * POSB;  HW = 1444; Wd = 38; stride = 16; off = 1083; in = in1; }
    else                { level = 2; pos0 = (lid - 58) * POSB;  HW = 5776; Wd = 76; stride = 8;  off = 5415; in = in2; }

    const int a   = tid >> 5;              // warp == anchor
    const int i   = tid & 31;
    const int pos = pos0 + i;
    const bool valid = (pos < HW);
    const int valid_rows = min(BLK, (HW - pos0) * 3);
    const int row_local  = i * 3 + a;
    const size_t row0 = (size_t)b * NTOT + off + (size_t)pos0 * 3;

    if (valid) {
        const float* inb = in + (size_t)b * 258 * HW;

        float ip = sigmoidf_fast(inb[(size_t)a * HW + pos]);

        const float* f = inb + (size_t)(3 + a * 85) * HW + pos;
        float dx   = f[0];
        float dy   = f[(size_t)1 * HW];
        float dw   = f[(size_t)2 * HW];
        float dh   = f[(size_t)3 * HW];
        float tobj = f[(size_t)4 * HW];

        float obj = sigmoidf_fast(tobj);
        // new_obj = obj^0.6 * ip^0.4 (both strictly in (0,1))
        float new_obj = exp2f(0.6f * __log2f(obj) + 0.4f * __log2f(ip));
        // sigmoid(de_sigmoid(x)) == x for x in (EPS, 1-EPS); inputs are
        // N(0,1) so new_obj stays far from both clip edges.
        float conf = fminf(fmaxf(new_obj, EPSV), 1.0f);

        int hh = pos / Wd;
        int ww = pos - hh * Wd;
        float x = (1.05f * sigmoidf_fast(dx) + (float)ww - 0.025f) * (float)stride;
        float y = (1.05f * sigmoidf_fast(dy) + (float)hh - 0.025f) * (float)stride;
        float bw = __expf(dw) * c_anch[level][a][0];
        float bh = __expf(dh) * c_anch[level][a][1];

        float imh = im_size[b * 2 + 0];
        float imw = im_size[b * 2 + 1];
        const float inv = 1.0f / 608.0f;   // H*stride = 608 for all levels
        float sx = imw * inv;
        float sy = imh * inv;

        float x0 = fmaxf((x - 0.5f * bw) * sx, 0.0f);
        float y0 = fmaxf((y - 0.5f * bh) * sy, 0.0f);
        float x1 = fminf((x + 0.5f * bw) * sx, imw);
        float y1 = fminf((y + 0.5f * bh) * sy, imh);

        *reinterpret_cast<float4*>(&s[SBOX + row_local * 4]) =
            make_float4(x0, y0, x1, y1);

        // all 80 classes -> smem, no barriers in between (disjoint writes)
        const float* p = f + (size_t)5 * HW;
        float* srow = &s[row_local * SSTR];
        #pragma unroll
        for (int g = 0; g < 20; ++g) {
            int c = g * 4;
            float4 v;
            v.x = conf * sigmoidf_fast(p[(size_t)(c + 0) * HW]);
            v.y = conf * sigmoidf_fast(p[(size_t)(c + 1) * HW]);
            v.z = conf * sigmoidf_fast(p[(size_t)(c + 2) * HW]);
            v.w = conf * sigmoidf_fast(p[(size_t)(c + 3) * HW]);
            *reinterpret_cast<float4*>(&srow[c]) = v;
        }
    }
    __syncthreads();

    // coalesced box store: 96 contiguous rows
    if (tid < valid_rows) {
        float4 v = *reinterpret_cast<const float4*>(&s[SBOX + tid * 4]);
        *reinterpret_cast<float4*>(&boxes[(row0 + tid) * 4]) = v;
    }

    // dense linear score sweep: 96 rows x 80 floats contiguous in global.
    // Each STG.128 warp-op covers 4 full 128B lines (wavefront floor).
    float* gbase = scores + row0 * NCLS;
    #pragma unroll
    for (int k = 0; k < 20; ++k) {
        int w  = (tid + k * BLK) * 4;     // word offset in the 96x80 region
        int rr = w / NCLS;
        int cc = w - rr * NCLS;
        if (rr < valid_rows) {
            float4 v = *reinterpret_cast<const float4*>(&s[rr * SSTR + cc]);
            *reinterpret_cast<float4*>(&gbase[w]) = v;
        }
    }
}

extern "C" void kernel_launch(void* const* d_in, const int* in_sizes, int n_in,
                              void* d_out, int out_size)
{
    const float* out0 = (const float*)d_in[0];
    const float* out1 = (const float*)d_in[1];
    const float* out2 = (const float*)d_in[2];
    const float* imsz = (const float*)d_in[3];

    float* boxes  = (float*)d_out;
    float* scores = boxes + (size_t)BATCH * NTOT * 4;

    yolo_fused_kernel<<<BATCH * LBLK, BLK>>>(out0, out1, out2, imsz, boxes, scores);
}

// round 14
// speedup vs baseline: 1.2336x; 1.1532x over previous
#include <cuda_runtime.h>
#include <cstddef>

// YOLOv3 head decode, fused, anchor-grouped, double-buffered pipeline.
// Block = 192 threads = 64 consecutive positions x 3 anchors of one (b,level).
// Warps anchor-pure -> plane loads perfectly coalesced.
// 5 chunks of 16 classes; two smem buffers, ONE barrier per chunk (5 total):
//   STS(k) -> bar(k) -> [prefetch LDGs for k+1 || LDS+STG store of k]
// Chunk k+1's global-load latency overlaps chunk k's store phase.
// Boxes stored directly from the compute phase (tiny traffic).
// Output: d_out = [boxes 16*22743*4][scores 16*22743*80].

#define NCLS 80
#define NTOT 22743
#define BATCH 16
#define EPSV 1e-7f
#define BLK 192
#define POSB 64               // positions per block
#define LBLK 120              // blocks per batch: 6 + 23 + 91
#define SROW 20               // smem words per row per 16-class chunk (+4 pad)

__constant__ float c_anch[3][3][2] = {
    {{116.0f, 90.0f}, {156.0f, 198.0f}, {373.0f, 326.0f}},
    {{ 30.0f, 61.0f}, { 62.0f,  45.0f}, { 59.0f, 119.0f}},
    {{ 10.0f, 13.0f}, { 16.0f,  30.0f}, { 33.0f,  23.0f}},
};

__device__ __forceinline__ float sigmoidf_fast(float x) {
    return __fdividef(1.0f, 1.0f + __expf(-x));
}

__global__ __launch_bounds__(BLK)
void yolo_fused_kernel(const float* __restrict__ in0,
                       const float* __restrict__ in1,
                       const float* __restrict__ in2,
                       const float* __restrict__ im_size,
                       float* __restrict__ boxes,
                       float* __restrict__ scores)
{
    __shared__ float s[2][BLK * SROW];   // 2 x 15 KB

    const int tid = threadIdx.x;
    const int b   = blockIdx.x / LBLK;
    const int lid = blockIdx.x - b * LBLK;

    int level, pos0, HW, Wd, stride, off;
    const float* in;
    if (lid < 6)        { level = 0; pos0 = lid * POSB;        HW = 361;  Wd = 19; stride = 32; off = 0;    in = in0; }
    else if (lid < 29)  { level = 1; pos0 = (lid - 6) * POSB;  HW = 1444; Wd = 38; stride = 16; off = 1083; in = in1; }
    else                { level = 2; pos0 = (lid - 29) * POSB; HW = 5776; Wd = 76; stride = 8;  off = 5415; in = in2; }

    const int a   = tid / POSB;            // warp-pure anchor id (2 warps each)
    const int i   = tid - a * POSB;
    const int pos = pos0 + i;
    const bool valid = (pos < HW);
    const int valid_rows = min(BLK, (HW - pos0) * 3);
    const int row_local  = i * 3 + a;
    const size_t row0 = (size_t)b * NTOT + off + (size_t)pos0 * 3;

    float conf = 0.0f;
    const float* p = in0;   // class-prob base for this thread's row
    float ld[16];

    if (valid) {
        const float* inb = in + (size_t)b * 258 * HW;

        float ip = sigmoidf_fast(inb[(size_t)a * HW + pos]);

        const float* f = inb + (size_t)(3 + a * 85) * HW + pos;
        float dx   = f[0];
        float dy   = f[(size_t)1 * HW];
        float dw   = f[(size_t)2 * HW];
        float dh   = f[(size_t)3 * HW];
        float tobj = f[(size_t)4 * HW];

        float obj = sigmoidf_fast(tobj);
        // new_obj = obj^0.6 * ip^0.4 (both strictly in (0,1))
        float new_obj = exp2f(0.6f * __log2f(obj) + 0.4f * __log2f(ip));
        // sigmoid(de_sigmoid(x)) == x for x in (EPS, 1-EPS); inputs are
        // N(0,1) so new_obj stays far from both clip edges.
        conf = fminf(fmaxf(new_obj, EPSV), 1.0f);

        int hh = pos / Wd;
        int ww = pos - hh * Wd;
        float x = (1.05f * sigmoidf_fast(dx) + (float)ww - 0.025f) * (float)stride;
        float y = (1.05f * sigmoidf_fast(dy) + (float)hh - 0.025f) * (float)stride;
        float bw = __expf(dw) * c_anch[level][a][0];
        float bh = __expf(dh) * c_anch[level][a][1];

        float imh = im_size[b * 2 + 0];
        float imw = im_size[b * 2 + 1];
        const float inv = 1.0f / 608.0f;   // H*stride = 608 for all levels
        float sx = imw * inv;
        float sy = imh * inv;

        float x0 = fmaxf((x - 0.5f * bw) * sx, 0.0f);
        float y0 = fmaxf((y - 0.5f * bh) * sy, 0.0f);
        float x1 = fminf((x + 0.5f * bw) * sx, imw);
        float y1 = fminf((y + 0.5f * bh) * sy, imh);

        // direct box store (one float4 per thread; tiny share of traffic)
        *reinterpret_cast<float4*>(&boxes[(row0 + row_local) * 4]) =
            make_float4(x0, y0, x1, y1);

        p = f + (size_t)5 * HW;

        // prologue: prefetch chunk-0 class logits
        #pragma unroll
        for (int j = 0; j < 16; ++j)
            ld[j] = p[(size_t)j * HW];
    }

    #pragma unroll
    for (int k = 0; k < 5; ++k) {
        float* buf = s[k & 1];

        // compute phase: sigmoid on prefetched values -> smem
        if (valid) {
            #pragma unroll
            for (int g = 0; g < 4; ++g) {
                float4 v;
                v.x = conf * sigmoidf_fast(ld[g * 4 + 0]);
                v.y = conf * sigmoidf_fast(ld[g * 4 + 1]);
                v.z = conf * sigmoidf_fast(ld[g * 4 + 2]);
                v.w = conf * sigmoidf_fast(ld[g * 4 + 3]);
                *reinterpret_cast<float4*>(&buf[row_local * SROW + g * 4]) = v;
            }
        }
        __syncthreads();

        // prefetch chunk k+1 (overlaps the store phase below)
        if (k < 4 && valid) {
            #pragma unroll
            for (int j = 0; j < 16; ++j)
                ld[j] = p[(size_t)((k + 1) * 16 + j) * HW];
        }

        // store phase: BLK rows x 16 floats, 4 lanes/row, 64B runs
        #pragma unroll
        for (int kk = 0; kk < 4; ++kk) {
            int idx = tid + kk * BLK;
            int rr  = idx >> 2;
            int q   = idx & 3;
            if (rr < valid_rows) {
                float4 v = *reinterpret_cast<const float4*>(&buf[rr * SROW + q * 4]);
                *reinterpret_cast<float4*>(&scores[(row0 + rr) * NCLS + k * 16 + q * 4]) = v;
            }
        }
    }
}

extern "C" void kernel_launch(void* const* d_in, const int* in_sizes, int n_in,
                              void* d_out, int out_size)
{
    const float* out0 = (const float*)d_in[0];
    const float* out1 = (const float*)d_in[1];
    const float* out2 = (const float*)d_in[2];
    const float* imsz = (const float*)d_in[3];

    float* boxes  = (float*)d_out;
    float* scores = boxes + (size_t)BATCH * NTOT * 4;

    yolo_fused_kernel<<<BATCH * LBLK, BLK>>>(out0, out1, out2, imsz, boxes, scores);
}